// round 9
// baseline (speedup 1.0000x reference)
#include <cuda_runtime.h>
#include <cuda_fp16.h>
#include <cstdint>
#include <math.h>

// Problem constants
#define NTOK 8192      // B*S
#define DIM  1024
#define NE   8
#define EPSV 1e-4f
#define WTHR 0.1f

// GEMM tile
#define BM 128
#define BN 64
#define BK 64
#define NKCH (DIM / BK)   // 16
#define NSTAGE 3

// smem (dynamic, bytes)
#define ASTRIDE 144                   // 64 fp16 (128B) + 16B pad
#define BSTRIDE 144                   // 64 fp16 (128B) + 16B pad
#define ABUF    (128 * ASTRIDE)       // 18432
#define BBUF    (64 * BSTRIDE)        // 9216
#define OFF_A   0
#define OFF_B   ABUF
#define STAGE_SZ (ABUF + BBUF)        // 27648
#define SM_TOK   0
#define SM_WT    512
#define SM_BIAS  1024
#define SM_TILES 1536
#define SM_TOTAL (SM_TILES + NSTAGE * STAGE_SZ)   // 84480

// -------- device scratch --------
__device__ int   g_cnt[NE];
__device__ int   g_tok[NE][NTOK];     // (token<<1) | slot
__device__ float g_wt [NE][NTOK];
__device__ __half g_xh[(size_t)NTOK * DIM];
__device__ __half g_wh[(size_t)NE * DIM * DIM];   // natural [e][d][f]
__device__ float g_part[2ull * NTOK * DIM];

// -------- helpers --------
__device__ __forceinline__ uint32_t smem_u32(const void* p) {
    uint32_t a;
    asm("{ .reg .u64 t; cvta.to.shared.u64 t, %1; cvt.u32.u64 %0, t; }" : "=r"(a) : "l"(p));
    return a;
}
__device__ __forceinline__ void ldsm_x4(uint32_t* r, uint32_t addr) {
    asm volatile("ldmatrix.sync.aligned.m8n8.x4.shared.b16 {%0,%1,%2,%3}, [%4];"
                 : "=r"(r[0]), "=r"(r[1]), "=r"(r[2]), "=r"(r[3]) : "r"(addr));
}
__device__ __forceinline__ void ldsm_x4_t(uint32_t* r, uint32_t addr) {
    asm volatile("ldmatrix.sync.aligned.m8n8.x4.trans.shared.b16 {%0,%1,%2,%3}, [%4];"
                 : "=r"(r[0]), "=r"(r[1]), "=r"(r[2]), "=r"(r[3]) : "r"(addr));
}
__device__ __forceinline__ void mma_f16(float* d, const uint32_t* a, uint32_t b0, uint32_t b1) {
    asm volatile(
        "mma.sync.aligned.m16n8k16.row.col.f32.f16.f16.f32 "
        "{%0,%1,%2,%3}, {%4,%5,%6,%7}, {%8,%9}, {%0,%1,%2,%3};"
        : "+f"(d[0]), "+f"(d[1]), "+f"(d[2]), "+f"(d[3])
        : "r"(a[0]), "r"(a[1]), "r"(a[2]), "r"(a[3]), "r"(b0), "r"(b1));
}
#define CPA16(dst, src) \
    asm volatile("cp.async.cg.shared.global [%0], [%1], 16;" :: "r"(dst), "l"(src) : "memory")
#define CPA_COMMIT() asm volatile("cp.async.commit_group;" ::: "memory")
#define CPA_WAIT0()  asm volatile("cp.async.wait_group 0;" ::: "memory")
#define CPA_WAIT1()  asm volatile("cp.async.wait_group 1;" ::: "memory")

// ================= kernels =================

__global__ void init_counts_kernel() {
    if (threadIdx.x < NE) g_cnt[threadIdx.x] = 0;
}

// gating + x->fp16 conversion fused: one warp per token
__global__ __launch_bounds__(256) void gating_kernel(
    const float* __restrict__ x, const float* __restrict__ gW, const float* __restrict__ gb)
{
    const int warp = threadIdx.x >> 5;
    const int lane = threadIdx.x & 31;
    const int t = blockIdx.x * 8 + warp;
    if (t >= NTOK) return;
    const float* xr = x + (size_t)t * DIM;

    float s[NE];
#pragma unroll
    for (int e = 0; e < NE; e++) s[e] = 0.0f;

#pragma unroll
    for (int i = 0; i < 8; i++) {
        const int d = i * 128 + lane * 4;
        float4 v = *(const float4*)(xr + d);
        // gate dot-products
        const float* g0 = gW + (size_t)d * NE;
#pragma unroll
        for (int e = 0; e < NE; e++) s[e] = fmaf(v.x, g0[e], s[e]);
#pragma unroll
        for (int e = 0; e < NE; e++) s[e] = fmaf(v.y, g0[NE + e], s[e]);
#pragma unroll
        for (int e = 0; e < NE; e++) s[e] = fmaf(v.z, g0[2 * NE + e], s[e]);
#pragma unroll
        for (int e = 0; e < NE; e++) s[e] = fmaf(v.w, g0[3 * NE + e], s[e]);
        // fused fp16 conversion of x
        __half2 h0 = __float22half2_rn(make_float2(v.x, v.y));
        __half2 h1 = __float22half2_rn(make_float2(v.z, v.w));
        *(uint2*)(g_xh + (size_t)t * DIM + d) =
            make_uint2(*(uint32_t*)&h0, *(uint32_t*)&h1);
    }

#pragma unroll
    for (int e = 0; e < NE; e++) {
#pragma unroll
        for (int off = 16; off > 0; off >>= 1)
            s[e] += __shfl_xor_sync(0xffffffffu, s[e], off);
    }
    if (lane == 0) {
        float p[NE];
        float m = -1e30f;
#pragma unroll
        for (int e = 0; e < NE; e++) {
            float sc = fmaxf(s[e] + gb[e], EPSV);
            p[e] = sc; m = fmaxf(m, sc);
        }
        float sum = 0.0f;
#pragma unroll
        for (int e = 0; e < NE; e++) { p[e] = expf(p[e] - m); sum += p[e]; }
        float inv = 1.0f / sum;
#pragma unroll
        for (int e = 0; e < NE; e++) p[e] *= inv;

        int i0 = 0; float b0 = p[0];
#pragma unroll
        for (int e = 1; e < NE; e++) if (p[e] > b0) { b0 = p[e]; i0 = e; }
        int i1 = (i0 == 0) ? 1 : 0; float b1 = -1.0f;
#pragma unroll
        for (int e = 0; e < NE; e++) if (e != i0 && p[e] > b1) { b1 = p[e]; i1 = e; }

        float w0 = fmaxf(b0, WTHR);
        float w1 = fmaxf(b1, WTHR);
        float invtot = 1.0f / (w0 + w1);
        float c0 = w0 * invtot * 0.5f;    // fold /K
        float c1 = w1 * invtot * 0.5f;

        int p0 = atomicAdd(&g_cnt[i0], 1);
        g_tok[i0][p0] = (t << 1) | 0; g_wt[i0][p0] = c0;
        int p1 = atomicAdd(&g_cnt[i1], 1);
        g_tok[i1][p1] = (t << 1) | 1; g_wt[i1][p1] = c1;
    }
}

// W fp32 -> fp16 (streaming)
__global__ __launch_bounds__(256) void wcvt_kernel(const float* __restrict__ W) {
    size_t i = ((size_t)blockIdx.x * 256 + threadIdx.x) * 4;
    float4 v = *(const float4*)(W + i);
    __half2 h0 = __float22half2_rn(make_float2(v.x, v.y));
    __half2 h1 = __float22half2_rn(make_float2(v.z, v.w));
    *(uint2*)(g_wh + i) = make_uint2(*(uint32_t*)&h0, *(uint32_t*)&h1);
}

// -------- fp16 expert GEMM, 3-stage cp.async pipeline, BM=128 x BN=64 --------
__global__ __launch_bounds__(256) void moe_gemm_kernel(const float* __restrict__ eb)
{
    extern __shared__ char smem[];
    const int e   = blockIdx.z;
    const int cnt = g_cnt[e];
    const int m0  = blockIdx.y * BM;
    if (m0 >= cnt) return;
    const int f0  = blockIdx.x * BN;

    const uint32_t sb = smem_u32(smem);
    const int tid  = threadIdx.x;
    const int lane = tid & 31;
    const int wid  = tid >> 5;
    const int wm   = wid & 1;     // 2 warp rows (64 m)
    const int wn   = wid >> 1;    // 4 warp cols (16 n)

    int*   stok  = (int*)(smem + SM_TOK);
    float* swt   = (float*)(smem + SM_WT);
    float* sbias = (float*)(smem + SM_BIAS);
    if (tid < BM) {
        int idx = m0 + tid;
        stok[tid] = (idx < cnt) ? g_tok[e][idx] : 0;
        swt[tid]  = (idx < cnt) ? g_wt[e][idx]  : 0.0f;
    }
    if (tid < BN) sbias[tid] = eb[(size_t)e * DIM + f0 + tid];
    __syncthreads();

    // copy mappings
    // A: 128 rows x 128B (8 x 16B): 1024 ops / 256 thr = 4 each
    int      atokr[4];
    uint32_t adst[4];
    const int acol = tid & 7;
#pragma unroll
    for (int j = 0; j < 4; j++) {
        int idx = tid + j * 256;
        int row = idx >> 3;
        atokr[j] = stok[row] >> 1;
        adst[j]  = (uint32_t)(row * ASTRIDE + acol * 16);
    }
    // B: 64 k-rows x 128B (8 x 16B): 512 ops / 256 thr = 2 each
    const int bcol = tid & 7;
    int      brow[2];
    uint32_t bdst[2];
#pragma unroll
    for (int j = 0; j < 2; j++) {
        int idx = tid + j * 256;
        brow[j] = idx >> 3;
        bdst[j] = (uint32_t)(brow[j] * BSTRIDE + bcol * 16);
    }
    const __half* Wh = g_wh + (size_t)e * DIM * DIM + f0 + bcol * 8;

    // prologue: issue chunks 0 and 1
#pragma unroll
    for (int pc = 0; pc < 2; pc++) {
        const uint32_t sp = sb + SM_TILES + pc * STAGE_SZ;
        const int k0 = pc * BK;
#pragma unroll
        for (int j = 0; j < 4; j++)
            CPA16(sp + OFF_A + adst[j], g_xh + (size_t)atokr[j] * DIM + k0 + acol * 8);
#pragma unroll
        for (int j = 0; j < 2; j++)
            CPA16(sp + OFF_B + bdst[j], Wh + (size_t)(k0 + brow[j]) * DIM);
        CPA_COMMIT();
    }

    float acc[4][2][4];
#pragma unroll
    for (int i = 0; i < 4; i++)
#pragma unroll
        for (int jj = 0; jj < 2; jj++)
#pragma unroll
            for (int r = 0; r < 4; r++) acc[i][jj][r] = 0.0f;

    const uint32_t a_off = (uint32_t)((wm * 64 + (lane & 15)) * ASTRIDE + ((lane >> 4) & 1) * 16);
    const uint32_t b_off = (uint32_t)((lane & 15) * BSTRIDE + wn * 32 + ((lane >> 4) & 1) * 16);

    int stage = 0;
    for (int c = 0; c < NKCH; c++) {
        if (c >= NKCH - 2) { CPA_WAIT0(); } else { CPA_WAIT1(); }
        __syncthreads();   // chunk c resident; all warps finished chunk c-1

        // issue chunk c+2 into the stage vacated by chunk c-1
        if (c + 2 < NKCH) {
            int nst = stage + 2; if (nst >= NSTAGE) nst -= NSTAGE;
            const uint32_t sn = sb + SM_TILES + nst * STAGE_SZ;
            const int k0 = (c + 2) * BK;
#pragma unroll
            for (int j = 0; j < 4; j++)
                CPA16(sn + OFF_A + adst[j], g_xh + (size_t)atokr[j] * DIM + k0 + acol * 8);
#pragma unroll
            for (int j = 0; j < 2; j++)
                CPA16(sn + OFF_B + bdst[j], Wh + (size_t)(k0 + brow[j]) * DIM);
            CPA_COMMIT();
        }

        const uint32_t sc = sb + SM_TILES + stage * STAGE_SZ;
#pragma unroll
        for (int ks = 0; ks < 4; ks++) {
            uint32_t ah[4][4];
#pragma unroll
            for (int mt = 0; mt < 4; mt++) {
                uint32_t ad = sc + OFF_A + a_off + (uint32_t)(mt * 16 * ASTRIDE + ks * 32);
                ldsm_x4(ah[mt], ad);
            }
            uint32_t bh[4];
            ldsm_x4_t(bh, sc + OFF_B + b_off + (uint32_t)(ks * 16 * BSTRIDE));
#pragma unroll
            for (int mt = 0; mt < 4; mt++) {
                mma_f16(acc[mt][0], ah[mt], bh[0], bh[1]);
                mma_f16(acc[mt][1], ah[mt], bh[2], bh[3]);
            }
        }
        stage++; if (stage >= NSTAGE) stage -= NSTAGE;
    }

    // ---- epilogue: write-once into g_part[slot][tok][f] ----
#pragma unroll
    for (int mt = 0; mt < 4; mt++) {
#pragma unroll
        for (int half = 0; half < 2; half++) {
            int m = wm * 64 + mt * 16 + (lane >> 2) + half * 8;
            if (m0 + m < cnt) {
                int te = stok[m];
                float w = swt[m];
                float* dst = g_part + ((size_t)(te & 1) * NTOK + (size_t)(te >> 1)) * DIM
                           + f0 + wn * 16;
#pragma unroll
                for (int nidx = 0; nidx < 2; nidx++) {
                    int cb = nidx * 8 + (lane & 3) * 2;
                    float v0 = w * (acc[mt][nidx][half * 2 + 0] + sbias[wn * 16 + cb]);
                    float v1 = w * (acc[mt][nidx][half * 2 + 1] + sbias[wn * 16 + cb + 1]);
                    *(float2*)(dst + cb) = make_float2(v0, v1);
                }
            }
        }
    }
}

// out = part0 + part1
__global__ __launch_bounds__(256) void combine_kernel(float* __restrict__ out) {
    size_t i = ((size_t)blockIdx.x * 256 + threadIdx.x) * 4;
    const float4 a = *(const float4*)(g_part + i);
    const float4 b = *(const float4*)(g_part + (size_t)NTOK * DIM + i);
    *(float4*)(out + i) = make_float4(a.x + b.x, a.y + b.y, a.z + b.z, a.w + b.w);
}

// ================= host =================
extern "C" void kernel_launch(void* const* d_in, const int* in_sizes, int n_in,
                              void* d_out, int out_size)
{
    const float* x  = (const float*)d_in[0];   // [4,2048,1024]
    const float* gW = (const float*)d_in[1];   // [1024,8]
    const float* gb = (const float*)d_in[2];   // [8]
    const float* eW = (const float*)d_in[3];   // [8,1024,1024]
    const float* eb = (const float*)d_in[4];   // [8,1024]
    float* out = (float*)d_out;
    (void)in_sizes; (void)n_in; (void)out_size;

    init_counts_kernel<<<1, 32>>>();
    gating_kernel<<<NTOK / 8, 256>>>(x, gW, gb);
    wcvt_kernel<<<(NE * DIM * DIM / 4) / 256, 256>>>(eW);

    cudaFuncSetAttribute(moe_gemm_kernel,
                         cudaFuncAttributeMaxDynamicSharedMemorySize, SM_TOTAL);
    dim3 grid(DIM / BN, NTOK / BM, NE);   // (16, 64, 8); inactive tiles exit early
    moe_gemm_kernel<<<grid, 256, SM_TOTAL>>>(eb);

    combine_kernel<<<(NTOK * DIM / 4) / 256, 256>>>(out);
}

// round 10
// speedup vs baseline: 1.6389x; 1.6389x over previous
#include <cuda_runtime.h>
#include <cuda_fp16.h>
#include <cstdint>
#include <math.h>

// Problem constants
#define NTOK 8192      // B*S
#define DIM  1024
#define NE   8
#define EPSV 1e-4f
#define WTHR 0.1f

// GEMM tile
#define BM 128
#define BN 128
#define BK 64
#define KHALF 512
#define NKCHH (KHALF / BK)    // 8 chunks per k-half
#define NSTAGE 3

// smem (dynamic, bytes)
#define ASTRIDE 144                   // 64 fp16 (128B) + 16B pad
#define BSTRIDE 272                   // 128 fp16 (256B) + 16B pad
#define ABUF    (128 * ASTRIDE)       // 18432
#define BBUF    (64 * BSTRIDE)        // 17408
#define OFF_A   0
#define OFF_B   ABUF
#define STAGE_SZ (ABUF + BBUF)        // 35840
#define SM_TOK   0
#define SM_WT    512
#define SM_BIAS  1024
#define SM_TILES 1536
#define SM_TOTAL (SM_TILES + NSTAGE * STAGE_SZ)   // 109056

// -------- device scratch --------
__device__ int   g_cnt[NE];
__device__ int   g_tok[NE][NTOK];     // (token<<1) | slot
__device__ float g_wt [NE][NTOK];
__device__ __half g_xh[(size_t)NTOK * DIM];
__device__ __half g_wh[(size_t)NE * DIM * DIM];   // natural [e][d][f]
__device__ float g_part[4ull * NTOK * DIM];       // planes: slot*2 + khalf

// -------- helpers --------
__device__ __forceinline__ uint32_t smem_u32(const void* p) {
    uint32_t a;
    asm("{ .reg .u64 t; cvta.to.shared.u64 t, %1; cvt.u32.u64 %0, t; }" : "=r"(a) : "l"(p));
    return a;
}
__device__ __forceinline__ void ldsm_x4(uint32_t* r, uint32_t addr) {
    asm volatile("ldmatrix.sync.aligned.m8n8.x4.shared.b16 {%0,%1,%2,%3}, [%4];"
                 : "=r"(r[0]), "=r"(r[1]), "=r"(r[2]), "=r"(r[3]) : "r"(addr));
}
__device__ __forceinline__ void ldsm_x4_t(uint32_t* r, uint32_t addr) {
    asm volatile("ldmatrix.sync.aligned.m8n8.x4.trans.shared.b16 {%0,%1,%2,%3}, [%4];"
                 : "=r"(r[0]), "=r"(r[1]), "=r"(r[2]), "=r"(r[3]) : "r"(addr));
}
__device__ __forceinline__ void mma_f16(float* d, const uint32_t* a, uint32_t b0, uint32_t b1) {
    asm volatile(
        "mma.sync.aligned.m16n8k16.row.col.f32.f16.f16.f32 "
        "{%0,%1,%2,%3}, {%4,%5,%6,%7}, {%8,%9}, {%0,%1,%2,%3};"
        : "+f"(d[0]), "+f"(d[1]), "+f"(d[2]), "+f"(d[3])
        : "r"(a[0]), "r"(a[1]), "r"(a[2]), "r"(a[3]), "r"(b0), "r"(b1));
}
#define CPA16(dst, src) \
    asm volatile("cp.async.cg.shared.global [%0], [%1], 16;" :: "r"(dst), "l"(src) : "memory")
#define CPA_COMMIT() asm volatile("cp.async.commit_group;" ::: "memory")
#define CPA_WAIT0()  asm volatile("cp.async.wait_group 0;" ::: "memory")
#define CPA_WAIT1()  asm volatile("cp.async.wait_group 1;" ::: "memory")

// ================= kernels =================

__global__ void init_counts_kernel() {
    if (threadIdx.x < NE) g_cnt[threadIdx.x] = 0;
}

// gating + x->fp16 conversion fused: one warp per token (validated R9)
__global__ __launch_bounds__(256) void gating_kernel(
    const float* __restrict__ x, const float* __restrict__ gW, const float* __restrict__ gb)
{
    const int warp = threadIdx.x >> 5;
    const int lane = threadIdx.x & 31;
    const int t = blockIdx.x * 8 + warp;
    if (t >= NTOK) return;
    const float* xr = x + (size_t)t * DIM;

    float s[NE];
#pragma unroll
    for (int e = 0; e < NE; e++) s[e] = 0.0f;

#pragma unroll
    for (int i = 0; i < 8; i++) {
        const int d = i * 128 + lane * 4;
        float4 v = *(const float4*)(xr + d);
        const float* g0 = gW + (size_t)d * NE;
#pragma unroll
        for (int e = 0; e < NE; e++) s[e] = fmaf(v.x, g0[e], s[e]);
#pragma unroll
        for (int e = 0; e < NE; e++) s[e] = fmaf(v.y, g0[NE + e], s[e]);
#pragma unroll
        for (int e = 0; e < NE; e++) s[e] = fmaf(v.z, g0[2 * NE + e], s[e]);
#pragma unroll
        for (int e = 0; e < NE; e++) s[e] = fmaf(v.w, g0[3 * NE + e], s[e]);
        __half2 h0 = __float22half2_rn(make_float2(v.x, v.y));
        __half2 h1 = __float22half2_rn(make_float2(v.z, v.w));
        *(uint2*)(g_xh + (size_t)t * DIM + d) =
            make_uint2(*(uint32_t*)&h0, *(uint32_t*)&h1);
    }

#pragma unroll
    for (int e = 0; e < NE; e++) {
#pragma unroll
        for (int off = 16; off > 0; off >>= 1)
            s[e] += __shfl_xor_sync(0xffffffffu, s[e], off);
    }
    if (lane == 0) {
        float p[NE];
        float m = -1e30f;
#pragma unroll
        for (int e = 0; e < NE; e++) {
            float sc = fmaxf(s[e] + gb[e], EPSV);
            p[e] = sc; m = fmaxf(m, sc);
        }
        float sum = 0.0f;
#pragma unroll
        for (int e = 0; e < NE; e++) { p[e] = expf(p[e] - m); sum += p[e]; }
        float inv = 1.0f / sum;
#pragma unroll
        for (int e = 0; e < NE; e++) p[e] *= inv;

        int i0 = 0; float b0 = p[0];
#pragma unroll
        for (int e = 1; e < NE; e++) if (p[e] > b0) { b0 = p[e]; i0 = e; }
        int i1 = (i0 == 0) ? 1 : 0; float b1 = -1.0f;
#pragma unroll
        for (int e = 0; e < NE; e++) if (e != i0 && p[e] > b1) { b1 = p[e]; i1 = e; }

        float w0 = fmaxf(b0, WTHR);
        float w1 = fmaxf(b1, WTHR);
        float invtot = 1.0f / (w0 + w1);
        float c0 = w0 * invtot * 0.5f;    // fold /K
        float c1 = w1 * invtot * 0.5f;

        int p0 = atomicAdd(&g_cnt[i0], 1);
        g_tok[i0][p0] = (t << 1) | 0; g_wt[i0][p0] = c0;
        int p1 = atomicAdd(&g_cnt[i1], 1);
        g_tok[i1][p1] = (t << 1) | 1; g_wt[i1][p1] = c1;
    }
}

// W fp32 -> fp16 (streaming)
__global__ __launch_bounds__(256) void wcvt_kernel(const float* __restrict__ W) {
    size_t i = ((size_t)blockIdx.x * 256 + threadIdx.x) * 4;
    float4 v = *(const float4*)(W + i);
    __half2 h0 = __float22half2_rn(make_float2(v.x, v.y));
    __half2 h1 = __float22half2_rn(make_float2(v.z, v.w));
    *(uint2*)(g_wh + i) = make_uint2(*(uint32_t*)&h0, *(uint32_t*)&h1);
}

// -------- fp16 expert GEMM, BM=128 x BN=128, k-split x2, 3-stage cp.async --------
// grid: (x = ftile*2 + khalf -> 16, y = m-tile -> 64, z = expert -> 8)
__global__ __launch_bounds__(256) void moe_gemm_kernel(const float* __restrict__ eb)
{
    extern __shared__ char smem[];
    const int e   = blockIdx.z;
    const int cnt = g_cnt[e];
    const int m0  = blockIdx.y * BM;
    if (m0 >= cnt) return;
    const int f0  = (blockIdx.x >> 1) * BN;
    const int kh  = blockIdx.x & 1;
    const int kb  = kh * KHALF;

    const uint32_t sb = smem_u32(smem);
    const int tid  = threadIdx.x;
    const int lane = tid & 31;
    const int wid  = tid >> 5;
    const int wm   = wid & 1;     // 2 warp rows (64 m)
    const int wn   = wid >> 1;    // 4 warp cols (32 n)

    int*   stok  = (int*)(smem + SM_TOK);
    float* swt   = (float*)(smem + SM_WT);
    float* sbias = (float*)(smem + SM_BIAS);
    if (tid < BM) {
        int idx = m0 + tid;
        stok[tid] = (idx < cnt) ? g_tok[e][idx] : 0;
        swt[tid]  = (idx < cnt) ? g_wt[e][idx]  : 0.0f;
        // bias added only by the khalf==0 plane
        sbias[tid] = kh ? 0.0f : eb[(size_t)e * DIM + f0 + tid];
    }
    __syncthreads();

    // copy mappings
    // A: 128 rows x 128B (8 x 16B): 1024 ops / 256 thr = 4 each
    int      atokr[4];
    uint32_t adst[4];
    const int acol = tid & 7;
#pragma unroll
    for (int j = 0; j < 4; j++) {
        int idx = tid + j * 256;
        int row = idx >> 3;
        atokr[j] = stok[row] >> 1;
        adst[j]  = (uint32_t)(row * ASTRIDE + acol * 16);
    }
    // B: 64 k-rows x 256B (16 x 16B): 1024 ops / 256 thr = 4 each
    const int bcol = tid & 15;
    int      brow[4];
    uint32_t bdst[4];
#pragma unroll
    for (int j = 0; j < 4; j++) {
        int idx = tid + j * 256;
        brow[j] = idx >> 4;
        bdst[j] = (uint32_t)(brow[j] * BSTRIDE + bcol * 16);
    }
    const __half* Wh = g_wh + (size_t)e * DIM * DIM + f0 + bcol * 8;

    // prologue: issue chunks 0,1 of this k-half
#pragma unroll
    for (int pc = 0; pc < 2; pc++) {
        const uint32_t sp = sb + SM_TILES + pc * STAGE_SZ;
        const int k0 = kb + pc * BK;
#pragma unroll
        for (int j = 0; j < 4; j++)
            CPA16(sp + OFF_A + adst[j], g_xh + (size_t)atokr[j] * DIM + k0 + acol * 8);
#pragma unroll
        for (int j = 0; j < 4; j++)
            CPA16(sp + OFF_B + bdst[j], Wh + (size_t)(k0 + brow[j]) * DIM);
        CPA_COMMIT();
    }

    float acc[4][4][4];
#pragma unroll
    for (int i = 0; i < 4; i++)
#pragma unroll
        for (int jj = 0; jj < 4; jj++)
#pragma unroll
            for (int r = 0; r < 4; r++) acc[i][jj][r] = 0.0f;

    const uint32_t a_off = (uint32_t)((wm * 64 + (lane & 15)) * ASTRIDE + ((lane >> 4) & 1) * 16);
    const uint32_t b_off = (uint32_t)((lane & 15) * BSTRIDE + wn * 64 + ((lane >> 4) & 1) * 16);

    int stage = 0;
    for (int c = 0; c < NKCHH; c++) {
        if (c >= NKCHH - 2) { CPA_WAIT0(); } else { CPA_WAIT1(); }
        __syncthreads();   // chunk c resident; all warps done computing chunk c-1

        // issue chunk c+2 into the stage vacated by chunk c-1
        if (c + 2 < NKCHH) {
            int nst = stage + 2; if (nst >= NSTAGE) nst -= NSTAGE;
            const uint32_t sn = sb + SM_TILES + nst * STAGE_SZ;
            const int k0 = kb + (c + 2) * BK;
#pragma unroll
            for (int j = 0; j < 4; j++)
                CPA16(sn + OFF_A + adst[j], g_xh + (size_t)atokr[j] * DIM + k0 + acol * 8);
#pragma unroll
            for (int j = 0; j < 4; j++)
                CPA16(sn + OFF_B + bdst[j], Wh + (size_t)(k0 + brow[j]) * DIM);
            CPA_COMMIT();
        }

        const uint32_t sc = sb + SM_TILES + stage * STAGE_SZ;
#pragma unroll
        for (int ks = 0; ks < 4; ks++) {
            uint32_t ah[4][4];
#pragma unroll
            for (int mt = 0; mt < 4; mt++) {
                uint32_t ad = sc + OFF_A + a_off + (uint32_t)(mt * 16 * ASTRIDE + ks * 32);
                ldsm_x4(ah[mt], ad);
            }
#pragma unroll
            for (int nb2 = 0; nb2 < 2; nb2++) {
                uint32_t bh[4];
                uint32_t bd = sc + OFF_B + b_off + (uint32_t)(ks * 16 * BSTRIDE + nb2 * 32);
                ldsm_x4_t(bh, bd);
#pragma unroll
                for (int mt = 0; mt < 4; mt++) {
                    mma_f16(acc[mt][nb2 * 2 + 0], ah[mt], bh[0], bh[1]);
                    mma_f16(acc[mt][nb2 * 2 + 1], ah[mt], bh[2], bh[3]);
                }
            }
        }
        stage++; if (stage >= NSTAGE) stage -= NSTAGE;
    }

    // ---- epilogue: write-once into plane (slot*2 + khalf) ----
#pragma unroll
    for (int mt = 0; mt < 4; mt++) {
#pragma unroll
        for (int half = 0; half < 2; half++) {
            int m = wm * 64 + mt * 16 + (lane >> 2) + half * 8;
            if (m0 + m < cnt) {
                int te = stok[m];
                float w = swt[m];
                int pl = (te & 1) * 2 + kh;
                float* dst = g_part + ((size_t)pl * NTOK + (size_t)(te >> 1)) * DIM
                           + f0 + wn * 32;
#pragma unroll
                for (int nidx = 0; nidx < 4; nidx++) {
                    int cb = nidx * 8 + (lane & 3) * 2;
                    float v0 = w * (acc[mt][nidx][half * 2 + 0] + sbias[wn * 32 + cb]);
                    float v1 = w * (acc[mt][nidx][half * 2 + 1] + sbias[wn * 32 + cb + 1]);
                    *(float2*)(dst + cb) = make_float2(v0, v1);
                }
            }
        }
    }
}

// out = sum of 4 partial planes
__global__ __launch_bounds__(256) void combine_kernel(float* __restrict__ out) {
    const size_t N = (size_t)NTOK * DIM;
    size_t i = ((size_t)blockIdx.x * 256 + threadIdx.x) * 4;
    const float4 a = *(const float4*)(g_part + i);
    const float4 b = *(const float4*)(g_part + N + i);
    const float4 c = *(const float4*)(g_part + 2 * N + i);
    const float4 d = *(const float4*)(g_part + 3 * N + i);
    *(float4*)(out + i) = make_float4(a.x + b.x + c.x + d.x,
                                      a.y + b.y + c.y + d.y,
                                      a.z + b.z + c.z + d.z,
                                      a.w + b.w + c.w + d.w);
}

// ================= host =================
extern "C" void kernel_launch(void* const* d_in, const int* in_sizes, int n_in,
                              void* d_out, int out_size)
{
    const float* x  = (const float*)d_in[0];   // [4,2048,1024]
    const float* gW = (const float*)d_in[1];   // [1024,8]
    const float* gb = (const float*)d_in[2];   // [8]
    const float* eW = (const float*)d_in[3];   // [8,1024,1024]
    const float* eb = (const float*)d_in[4];   // [8,1024]
    float* out = (float*)d_out;
    (void)in_sizes; (void)n_in; (void)out_size;

    init_counts_kernel<<<1, 32>>>();
    gating_kernel<<<NTOK / 8, 256>>>(x, gW, gb);
    wcvt_kernel<<<(NE * DIM * DIM / 4) / 256, 256>>>(eW);

    cudaFuncSetAttribute(moe_gemm_kernel,
                         cudaFuncAttributeMaxDynamicSharedMemorySize, SM_TOTAL);
    dim3 grid(2 * DIM / BN, NTOK / BM, NE);   // (16, 64, 8); inactive tiles exit early
    moe_gemm_kernel<<<grid, 256, SM_TOTAL>>>(eb);

    combine_kernel<<<(NTOK * DIM / 4) / 256, 256>>>(out);
}

// round 11
// speedup vs baseline: 1.6617x; 1.0139x over previous
#include <cuda_runtime.h>
#include <cuda_fp16.h>
#include <cstdint>
#include <math.h>

// Problem constants
#define NTOK 8192      // B*S
#define DIM  1024
#define NE   8
#define EPSV 1e-4f
#define WTHR 0.1f

// GEMM tile
#define BM 128
#define BN 128
#define BK 64
#define KHALF 512
#define NKCHH (KHALF / BK)    // 8 chunks per k-half
#define NSTAGE 2

// smem (dynamic, bytes)
#define ASTRIDE 144                   // 64 fp16 (128B) + 16B pad
#define BSTRIDE 272                   // 128 fp16 (256B) + 16B pad
#define ABUF    (128 * ASTRIDE)       // 18432
#define BBUF    (64 * BSTRIDE)        // 17408
#define OFF_A   0
#define OFF_B   ABUF
#define STAGE_SZ (ABUF + BBUF)        // 35840
#define SM_TOK   0
#define SM_WT    512
#define SM_BIAS  1024
#define SM_TILES 1536
#define SM_TOTAL (SM_TILES + NSTAGE * STAGE_SZ)   // 73216

// -------- device scratch --------
__device__ int   g_cnt[NE];
__device__ int   g_tok[NE][NTOK];     // (token<<1) | slot
__device__ float g_wt [NE][NTOK];
__device__ __half g_xh[(size_t)NTOK * DIM];
__device__ __half g_wh[(size_t)NE * DIM * DIM];   // natural [e][d][f]

// -------- helpers --------
__device__ __forceinline__ uint32_t smem_u32(const void* p) {
    uint32_t a;
    asm("{ .reg .u64 t; cvta.to.shared.u64 t, %1; cvt.u32.u64 %0, t; }" : "=r"(a) : "l"(p));
    return a;
}
__device__ __forceinline__ void ldsm_x4(uint32_t* r, uint32_t addr) {
    asm volatile("ldmatrix.sync.aligned.m8n8.x4.shared.b16 {%0,%1,%2,%3}, [%4];"
                 : "=r"(r[0]), "=r"(r[1]), "=r"(r[2]), "=r"(r[3]) : "r"(addr));
}
__device__ __forceinline__ void ldsm_x4_t(uint32_t* r, uint32_t addr) {
    asm volatile("ldmatrix.sync.aligned.m8n8.x4.trans.shared.b16 {%0,%1,%2,%3}, [%4];"
                 : "=r"(r[0]), "=r"(r[1]), "=r"(r[2]), "=r"(r[3]) : "r"(addr));
}
__device__ __forceinline__ void mma_f16(float* d, const uint32_t* a, uint32_t b0, uint32_t b1) {
    asm volatile(
        "mma.sync.aligned.m16n8k16.row.col.f32.f16.f16.f32 "
        "{%0,%1,%2,%3}, {%4,%5,%6,%7}, {%8,%9}, {%0,%1,%2,%3};"
        : "+f"(d[0]), "+f"(d[1]), "+f"(d[2]), "+f"(d[3])
        : "r"(a[0]), "r"(a[1]), "r"(a[2]), "r"(a[3]), "r"(b0), "r"(b1));
}
#define CPA16(dst, src) \
    asm volatile("cp.async.cg.shared.global [%0], [%1], 16;" :: "r"(dst), "l"(src) : "memory")
#define CPA_COMMIT() asm volatile("cp.async.commit_group;" ::: "memory")
#define CPA_WAIT0()  asm volatile("cp.async.wait_group 0;" ::: "memory")

// ================= kernels =================

__global__ void init_counts_kernel() {
    if (threadIdx.x < NE) g_cnt[threadIdx.x] = 0;
}

// gating + x->fp16 conversion fused: one warp per token
__global__ __launch_bounds__(256) void gating_kernel(
    const float* __restrict__ x, const float* __restrict__ gW, const float* __restrict__ gb)
{
    const int warp = threadIdx.x >> 5;
    const int lane = threadIdx.x & 31;
    const int t = blockIdx.x * 8 + warp;
    if (t >= NTOK) return;
    const float* xr = x + (size_t)t * DIM;

    float s[NE];
#pragma unroll
    for (int e = 0; e < NE; e++) s[e] = 0.0f;

#pragma unroll
    for (int i = 0; i < 8; i++) {
        const int d = i * 128 + lane * 4;
        float4 v = *(const float4*)(xr + d);
        const float* g0 = gW + (size_t)d * NE;
#pragma unroll
        for (int e = 0; e < NE; e++) s[e] = fmaf(v.x, g0[e], s[e]);
#pragma unroll
        for (int e = 0; e < NE; e++) s[e] = fmaf(v.y, g0[NE + e], s[e]);
#pragma unroll
        for (int e = 0; e < NE; e++) s[e] = fmaf(v.z, g0[2 * NE + e], s[e]);
#pragma unroll
        for (int e = 0; e < NE; e++) s[e] = fmaf(v.w, g0[3 * NE + e], s[e]);
        __half2 h0 = __float22half2_rn(make_float2(v.x, v.y));
        __half2 h1 = __float22half2_rn(make_float2(v.z, v.w));
        *(uint2*)(g_xh + (size_t)t * DIM + d) =
            make_uint2(*(uint32_t*)&h0, *(uint32_t*)&h1);
    }

#pragma unroll
    for (int e = 0; e < NE; e++) {
#pragma unroll
        for (int off = 16; off > 0; off >>= 1)
            s[e] += __shfl_xor_sync(0xffffffffu, s[e], off);
    }
    if (lane == 0) {
        float p[NE];
        float m = -1e30f;
#pragma unroll
        for (int e = 0; e < NE; e++) {
            float sc = fmaxf(s[e] + gb[e], EPSV);
            p[e] = sc; m = fmaxf(m, sc);
        }
        float sum = 0.0f;
#pragma unroll
        for (int e = 0; e < NE; e++) { p[e] = expf(p[e] - m); sum += p[e]; }
        float inv = 1.0f / sum;
#pragma unroll
        for (int e = 0; e < NE; e++) p[e] *= inv;

        int i0 = 0; float b0 = p[0];
#pragma unroll
        for (int e = 1; e < NE; e++) if (p[e] > b0) { b0 = p[e]; i0 = e; }
        int i1 = (i0 == 0) ? 1 : 0; float b1 = -1.0f;
#pragma unroll
        for (int e = 0; e < NE; e++) if (e != i0 && p[e] > b1) { b1 = p[e]; i1 = e; }

        float w0 = fmaxf(b0, WTHR);
        float w1 = fmaxf(b1, WTHR);
        float invtot = 1.0f / (w0 + w1);
        float c0 = w0 * invtot * 0.5f;    // fold /K
        float c1 = w1 * invtot * 0.5f;

        int p0 = atomicAdd(&g_cnt[i0], 1);
        g_tok[i0][p0] = (t << 1) | 0; g_wt[i0][p0] = c0;
        int p1 = atomicAdd(&g_cnt[i1], 1);
        g_tok[i1][p1] = (t << 1) | 1; g_wt[i1][p1] = c1;
    }
}

// W fp32 -> fp16 (streaming)
__global__ __launch_bounds__(256) void wcvt_kernel(const float* __restrict__ W) {
    size_t i = ((size_t)blockIdx.x * 256 + threadIdx.x) * 4;
    float4 v = *(const float4*)(W + i);
    __half2 h0 = __float22half2_rn(make_float2(v.x, v.y));
    __half2 h1 = __float22half2_rn(make_float2(v.z, v.w));
    *(uint2*)(g_wh + i) = make_uint2(*(uint32_t*)&h0, *(uint32_t*)&h1);
}

// -------- fp16 expert GEMM, BM=128 x BN=128, k-split x2, 2-stage cp.async --------
// grid: (x = ftile*2 + khalf -> 16, y = m-tile -> 64, z = expert -> 8)
// epilogue: atomicAdd into out (<=4 commutative addends per element)
__global__ __launch_bounds__(256) void moe_gemm_kernel(
    const float* __restrict__ eb, float* __restrict__ out)
{
    extern __shared__ char smem[];
    const int e   = blockIdx.z;
    const int cnt = g_cnt[e];
    const int m0  = blockIdx.y * BM;
    if (m0 >= cnt) return;
    const int f0  = (blockIdx.x >> 1) * BN;
    const int kh  = blockIdx.x & 1;
    const int kb  = kh * KHALF;

    const uint32_t sb = smem_u32(smem);
    const int tid  = threadIdx.x;
    const int lane = tid & 31;
    const int wid  = tid >> 5;
    const int wm   = wid & 1;     // 2 warp rows (64 m)
    const int wn   = wid >> 1;    // 4 warp cols (32 n)

    int*   stok  = (int*)(smem + SM_TOK);
    float* swt   = (float*)(smem + SM_WT);
    float* sbias = (float*)(smem + SM_BIAS);
    if (tid < BM) {
        int idx = m0 + tid;
        stok[tid] = (idx < cnt) ? g_tok[e][idx] : 0;
        swt[tid]  = (idx < cnt) ? g_wt[e][idx]  : 0.0f;
        sbias[tid] = kh ? 0.0f : eb[(size_t)e * DIM + f0 + tid];  // bias once per k-split
    }
    __syncthreads();

    // copy mappings (R7-validated)
    int      atokr[4];
    uint32_t adst[4];
    const int acol = tid & 7;
#pragma unroll
    for (int j = 0; j < 4; j++) {
        int idx = tid + j * 256;
        int row = idx >> 3;
        atokr[j] = stok[row] >> 1;
        adst[j]  = (uint32_t)(row * ASTRIDE + acol * 16);
    }
    const int bcol = tid & 15;
    int      brow[4];
    uint32_t bdst[4];
#pragma unroll
    for (int j = 0; j < 4; j++) {
        int idx = tid + j * 256;
        brow[j] = idx >> 4;
        bdst[j] = (uint32_t)(brow[j] * BSTRIDE + bcol * 16);
    }
    const __half* Wh = g_wh + (size_t)e * DIM * DIM + f0 + bcol * 8;

    // prologue: chunk 0 -> stage 0
    {
        const uint32_t s0 = sb + SM_TILES;
#pragma unroll
        for (int j = 0; j < 4; j++)
            CPA16(s0 + OFF_A + adst[j], g_xh + (size_t)atokr[j] * DIM + kb + acol * 8);
#pragma unroll
        for (int j = 0; j < 4; j++)
            CPA16(s0 + OFF_B + bdst[j], Wh + (size_t)(kb + brow[j]) * DIM);
        CPA_COMMIT();
    }

    float acc[4][4][4];
#pragma unroll
    for (int i = 0; i < 4; i++)
#pragma unroll
        for (int jj = 0; jj < 4; jj++)
#pragma unroll
            for (int r = 0; r < 4; r++) acc[i][jj][r] = 0.0f;

    const uint32_t a_off = (uint32_t)((wm * 64 + (lane & 15)) * ASTRIDE + ((lane >> 4) & 1) * 16);
    const uint32_t b_off = (uint32_t)((lane & 15) * BSTRIDE + wn * 64 + ((lane >> 4) & 1) * 16);

    for (int c = 0; c < NKCHH; c++) {
        CPA_WAIT0();
        __syncthreads();

        if (c + 1 < NKCHH) {
            const uint32_t sn = sb + SM_TILES + ((c + 1) & 1) * STAGE_SZ;
            const int k0 = kb + (c + 1) * BK;
#pragma unroll
            for (int j = 0; j < 4; j++)
                CPA16(sn + OFF_A + adst[j], g_xh + (size_t)atokr[j] * DIM + k0 + acol * 8);
#pragma unroll
            for (int j = 0; j < 4; j++)
                CPA16(sn + OFF_B + bdst[j], Wh + (size_t)(k0 + brow[j]) * DIM);
            CPA_COMMIT();
        }

        const uint32_t sc = sb + SM_TILES + (c & 1) * STAGE_SZ;
#pragma unroll
        for (int ks = 0; ks < 4; ks++) {
            uint32_t ah[4][4];
#pragma unroll
            for (int mt = 0; mt < 4; mt++) {
                uint32_t ad = sc + OFF_A + a_off + (uint32_t)(mt * 16 * ASTRIDE + ks * 32);
                ldsm_x4(ah[mt], ad);
            }
#pragma unroll
            for (int nb2 = 0; nb2 < 2; nb2++) {
                uint32_t bh[4];
                uint32_t bd = sc + OFF_B + b_off + (uint32_t)(ks * 16 * BSTRIDE + nb2 * 32);
                ldsm_x4_t(bh, bd);
#pragma unroll
                for (int mt = 0; mt < 4; mt++) {
                    mma_f16(acc[mt][nb2 * 2 + 0], ah[mt], bh[0], bh[1]);
                    mma_f16(acc[mt][nb2 * 2 + 1], ah[mt], bh[2], bh[3]);
                }
            }
        }
        __syncthreads();
    }

    // ---- epilogue: atomicAdd into out (commutative; <=4 addends/element) ----
#pragma unroll
    for (int mt = 0; mt < 4; mt++) {
#pragma unroll
        for (int half = 0; half < 2; half++) {
            int m = wm * 64 + mt * 16 + (lane >> 2) + half * 8;
            if (m0 + m < cnt) {
                int te = stok[m];
                float w = swt[m];
                float* dst = out + (size_t)(te >> 1) * DIM + f0 + wn * 32;
#pragma unroll
                for (int nidx = 0; nidx < 4; nidx++) {
                    int cb = nidx * 8 + (lane & 3) * 2;
                    float v0 = w * (acc[mt][nidx][half * 2 + 0] + sbias[wn * 32 + cb]);
                    float v1 = w * (acc[mt][nidx][half * 2 + 1] + sbias[wn * 32 + cb + 1]);
                    atomicAdd(dst + cb, v0);
                    atomicAdd(dst + cb + 1, v1);
                }
            }
        }
    }
}

// ================= host =================
extern "C" void kernel_launch(void* const* d_in, const int* in_sizes, int n_in,
                              void* d_out, int out_size)
{
    const float* x  = (const float*)d_in[0];   // [4,2048,1024]
    const float* gW = (const float*)d_in[1];   // [1024,8]
    const float* gb = (const float*)d_in[2];   // [8]
    const float* eW = (const float*)d_in[3];   // [8,1024,1024]
    const float* eb = (const float*)d_in[4];   // [8,1024]
    float* out = (float*)d_out;
    (void)in_sizes; (void)n_in;

    cudaMemsetAsync(d_out, 0, (size_t)out_size * sizeof(float));
    init_counts_kernel<<<1, 32>>>();
    gating_kernel<<<NTOK / 8, 256>>>(x, gW, gb);
    wcvt_kernel<<<(NE * DIM * DIM / 4) / 256, 256>>>(eW);

    cudaFuncSetAttribute(moe_gemm_kernel,
                         cudaFuncAttributeMaxDynamicSharedMemorySize, SM_TOTAL);
    dim3 grid(2 * DIM / BN, NTOK / BM, NE);   // (16, 64, 8); inactive tiles exit early
    moe_gemm_kernel<<<grid, 256, SM_TOTAL>>>(eb, out);
}

// round 12
// speedup vs baseline: 1.7712x; 1.0659x over previous
#include <cuda_runtime.h>
#include <cuda_fp16.h>
#include <cstdint>
#include <math.h>

// Problem constants
#define NTOK 8192      // B*S
#define DIM  1024
#define NE   8
#define EPSV 1e-4f
#define WTHR 0.1f

// GEMM tile (R7-proven config)
#define BM 128
#define BN 128
#define BK 64
#define NKCH (DIM / BK)   // 16

// smem (dynamic, bytes)
#define ASTRIDE 144                   // 64 fp16 (128B) + 16B pad
#define BSTRIDE 272                   // 128 fp16 (256B) + 16B pad
#define ABUF    (128 * ASTRIDE)       // 18432
#define BBUF    (64 * BSTRIDE)        // 17408
#define OFF_A   0
#define OFF_B   ABUF
#define STAGE_SZ (ABUF + BBUF)        // 35840
#define SM_TOK   0
#define SM_WT    512
#define SM_BIAS  1024
#define SM_TILES 1536
#define SM_TOTAL (SM_TILES + 2 * STAGE_SZ)   // 73216

// -------- device scratch --------
__device__ int   g_cnt[NE];
__device__ int   g_tok[NE][NTOK];     // (token<<1) | slot
__device__ float g_wt [NE][NTOK];
__device__ __half g_xh[(size_t)NTOK * DIM];
__device__ __half g_wh[(size_t)NE * DIM * DIM];   // natural [e][d][f]
__device__ float g_part[2ull * NTOK * DIM];

// -------- helpers --------
__device__ __forceinline__ uint32_t smem_u32(const void* p) {
    uint32_t a;
    asm("{ .reg .u64 t; cvta.to.shared.u64 t, %1; cvt.u32.u64 %0, t; }" : "=r"(a) : "l"(p));
    return a;
}
__device__ __forceinline__ void ldsm_x4(uint32_t* r, uint32_t addr) {
    asm volatile("ldmatrix.sync.aligned.m8n8.x4.shared.b16 {%0,%1,%2,%3}, [%4];"
                 : "=r"(r[0]), "=r"(r[1]), "=r"(r[2]), "=r"(r[3]) : "r"(addr));
}
__device__ __forceinline__ void ldsm_x4_t(uint32_t* r, uint32_t addr) {
    asm volatile("ldmatrix.sync.aligned.m8n8.x4.trans.shared.b16 {%0,%1,%2,%3}, [%4];"
                 : "=r"(r[0]), "=r"(r[1]), "=r"(r[2]), "=r"(r[3]) : "r"(addr));
}
__device__ __forceinline__ void mma_f16(float* d, const uint32_t* a, uint32_t b0, uint32_t b1) {
    asm volatile(
        "mma.sync.aligned.m16n8k16.row.col.f32.f16.f16.f32 "
        "{%0,%1,%2,%3}, {%4,%5,%6,%7}, {%8,%9}, {%0,%1,%2,%3};"
        : "+f"(d[0]), "+f"(d[1]), "+f"(d[2]), "+f"(d[3])
        : "r"(a[0]), "r"(a[1]), "r"(a[2]), "r"(a[3]), "r"(b0), "r"(b1));
}
#define CPA16(dst, src) \
    asm volatile("cp.async.cg.shared.global [%0], [%1], 16;" :: "r"(dst), "l"(src) : "memory")
#define CPA_COMMIT() asm volatile("cp.async.commit_group;" ::: "memory")
#define CPA_WAIT0()  asm volatile("cp.async.wait_group 0;" ::: "memory")

// ================= kernels =================

__global__ void init_counts_kernel() {
    if (threadIdx.x < NE) g_cnt[threadIdx.x] = 0;
}

// gating + x->fp16 conversion fused: one warp per token (validated R9-R11)
__global__ __launch_bounds__(256) void gating_kernel(
    const float* __restrict__ x, const float* __restrict__ gW, const float* __restrict__ gb)
{
    const int warp = threadIdx.x >> 5;
    const int lane = threadIdx.x & 31;
    const int t = blockIdx.x * 8 + warp;
    if (t >= NTOK) return;
    const float* xr = x + (size_t)t * DIM;

    float s[NE];
#pragma unroll
    for (int e = 0; e < NE; e++) s[e] = 0.0f;

#pragma unroll
    for (int i = 0; i < 8; i++) {
        const int d = i * 128 + lane * 4;
        float4 v = *(const float4*)(xr + d);
        const float* g0 = gW + (size_t)d * NE;
#pragma unroll
        for (int e = 0; e < NE; e++) s[e] = fmaf(v.x, g0[e], s[e]);
#pragma unroll
        for (int e = 0; e < NE; e++) s[e] = fmaf(v.y, g0[NE + e], s[e]);
#pragma unroll
        for (int e = 0; e < NE; e++) s[e] = fmaf(v.z, g0[2 * NE + e], s[e]);
#pragma unroll
        for (int e = 0; e < NE; e++) s[e] = fmaf(v.w, g0[3 * NE + e], s[e]);
        __half2 h0 = __float22half2_rn(make_float2(v.x, v.y));
        __half2 h1 = __float22half2_rn(make_float2(v.z, v.w));
        *(uint2*)(g_xh + (size_t)t * DIM + d) =
            make_uint2(*(uint32_t*)&h0, *(uint32_t*)&h1);
    }

#pragma unroll
    for (int e = 0; e < NE; e++) {
#pragma unroll
        for (int off = 16; off > 0; off >>= 1)
            s[e] += __shfl_xor_sync(0xffffffffu, s[e], off);
    }
    if (lane == 0) {
        float p[NE];
        float m = -1e30f;
#pragma unroll
        for (int e = 0; e < NE; e++) {
            float sc = fmaxf(s[e] + gb[e], EPSV);
            p[e] = sc; m = fmaxf(m, sc);
        }
        float sum = 0.0f;
#pragma unroll
        for (int e = 0; e < NE; e++) { p[e] = expf(p[e] - m); sum += p[e]; }
        float inv = 1.0f / sum;
#pragma unroll
        for (int e = 0; e < NE; e++) p[e] *= inv;

        int i0 = 0; float b0 = p[0];
#pragma unroll
        for (int e = 1; e < NE; e++) if (p[e] > b0) { b0 = p[e]; i0 = e; }
        int i1 = (i0 == 0) ? 1 : 0; float b1 = -1.0f;
#pragma unroll
        for (int e = 0; e < NE; e++) if (e != i0 && p[e] > b1) { b1 = p[e]; i1 = e; }

        float w0 = fmaxf(b0, WTHR);
        float w1 = fmaxf(b1, WTHR);
        float invtot = 1.0f / (w0 + w1);
        float c0 = w0 * invtot * 0.5f;    // fold /K
        float c1 = w1 * invtot * 0.5f;

        int p0 = atomicAdd(&g_cnt[i0], 1);
        g_tok[i0][p0] = (t << 1) | 0; g_wt[i0][p0] = c0;
        int p1 = atomicAdd(&g_cnt[i1], 1);
        g_tok[i1][p1] = (t << 1) | 1; g_wt[i1][p1] = c1;
    }
}

// W fp32 -> fp16 (streaming)
__global__ __launch_bounds__(256) void wcvt_kernel(const float* __restrict__ W) {
    size_t i = ((size_t)blockIdx.x * 256 + threadIdx.x) * 4;
    float4 v = *(const float4*)(W + i);
    __half2 h0 = __float22half2_rn(make_float2(v.x, v.y));
    __half2 h1 = __float22half2_rn(make_float2(v.z, v.w));
    *(uint2*)(g_wh + i) = make_uint2(*(uint32_t*)&h0, *(uint32_t*)&h1);
}

// -------- fp16 expert GEMM, BM=128 x BN=128, full-K, 2-stage cp.async (R7) --------
__global__ __launch_bounds__(256) void moe_gemm_kernel(const float* __restrict__ eb)
{
    extern __shared__ char smem[];
    const int e   = blockIdx.z;
    const int cnt = g_cnt[e];
    const int m0  = blockIdx.y * BM;
    if (m0 >= cnt) return;
    const int f0  = blockIdx.x * BN;

    const uint32_t sb = smem_u32(smem);
    const int tid  = threadIdx.x;
    const int lane = tid & 31;
    const int wid  = tid >> 5;
    const int wm   = wid & 1;     // 2 warp rows (64 m)
    const int wn   = wid >> 1;    // 4 warp cols (32 n)

    int*   stok  = (int*)(smem + SM_TOK);
    float* swt   = (float*)(smem + SM_WT);
    float* sbias = (float*)(smem + SM_BIAS);
    if (tid < BM) {
        int idx = m0 + tid;
        stok[tid] = (idx < cnt) ? g_tok[e][idx] : 0;
        swt[tid]  = (idx < cnt) ? g_wt[e][idx]  : 0.0f;
        sbias[tid] = eb[(size_t)e * DIM + f0 + tid];
    }
    __syncthreads();

    // copy mappings
    int      atokr[4];
    uint32_t adst[4];
    const int acol = tid & 7;
#pragma unroll
    for (int j = 0; j < 4; j++) {
        int idx = tid + j * 256;
        int row = idx >> 3;
        atokr[j] = stok[row] >> 1;
        adst[j]  = (uint32_t)(row * ASTRIDE + acol * 16);
    }
    const int bcol = tid & 15;
    int      brow[4];
    uint32_t bdst[4];
#pragma unroll
    for (int j = 0; j < 4; j++) {
        int idx = tid + j * 256;
        brow[j] = idx >> 4;
        bdst[j] = (uint32_t)(brow[j] * BSTRIDE + bcol * 16);
    }
    const __half* Wh = g_wh + (size_t)e * DIM * DIM + f0 + bcol * 8;

    // prologue: chunk 0 -> stage 0
    {
        const uint32_t s0 = sb + SM_TILES;
#pragma unroll
        for (int j = 0; j < 4; j++)
            CPA16(s0 + OFF_A + adst[j], g_xh + (size_t)atokr[j] * DIM + acol * 8);
#pragma unroll
        for (int j = 0; j < 4; j++)
            CPA16(s0 + OFF_B + bdst[j], Wh + (size_t)brow[j] * DIM);
        CPA_COMMIT();
    }

    float acc[4][4][4];
#pragma unroll
    for (int i = 0; i < 4; i++)
#pragma unroll
        for (int jj = 0; jj < 4; jj++)
#pragma unroll
            for (int r = 0; r < 4; r++) acc[i][jj][r] = 0.0f;

    const uint32_t a_off = (uint32_t)((wm * 64 + (lane & 15)) * ASTRIDE + ((lane >> 4) & 1) * 16);
    const uint32_t b_off = (uint32_t)((lane & 15) * BSTRIDE + wn * 64 + ((lane >> 4) & 1) * 16);

    for (int c = 0; c < NKCH; c++) {
        CPA_WAIT0();
        __syncthreads();

        if (c + 1 < NKCH) {
            const uint32_t sn = sb + SM_TILES + ((c + 1) & 1) * STAGE_SZ;
            const int k0 = (c + 1) * BK;
#pragma unroll
            for (int j = 0; j < 4; j++)
                CPA16(sn + OFF_A + adst[j], g_xh + (size_t)atokr[j] * DIM + k0 + acol * 8);
#pragma unroll
            for (int j = 0; j < 4; j++)
                CPA16(sn + OFF_B + bdst[j], Wh + (size_t)(k0 + brow[j]) * DIM);
            CPA_COMMIT();
        }

        const uint32_t sc = sb + SM_TILES + (c & 1) * STAGE_SZ;
#pragma unroll
        for (int ks = 0; ks < 4; ks++) {
            uint32_t ah[4][4];
#pragma unroll
            for (int mt = 0; mt < 4; mt++) {
                uint32_t ad = sc + OFF_A + a_off + (uint32_t)(mt * 16 * ASTRIDE + ks * 32);
                ldsm_x4(ah[mt], ad);
            }
#pragma unroll
            for (int nb2 = 0; nb2 < 2; nb2++) {
                uint32_t bh[4];
                uint32_t bd = sc + OFF_B + b_off + (uint32_t)(ks * 16 * BSTRIDE + nb2 * 32);
                ldsm_x4_t(bh, bd);
#pragma unroll
                for (int mt = 0; mt < 4; mt++) {
                    mma_f16(acc[mt][nb2 * 2 + 0], ah[mt], bh[0], bh[1]);
                    mma_f16(acc[mt][nb2 * 2 + 1], ah[mt], bh[2], bh[3]);
                }
            }
        }
        __syncthreads();
    }

    // ---- epilogue: write-once into g_part[slot][tok][f] ----
#pragma unroll
    for (int mt = 0; mt < 4; mt++) {
#pragma unroll
        for (int half = 0; half < 2; half++) {
            int m = wm * 64 + mt * 16 + (lane >> 2) + half * 8;
            if (m0 + m < cnt) {
                int te = stok[m];
                float w = swt[m];
                float* dst = g_part + ((size_t)(te & 1) * NTOK + (size_t)(te >> 1)) * DIM
                           + f0 + wn * 32;
#pragma unroll
                for (int nidx = 0; nidx < 4; nidx++) {
                    int cb = nidx * 8 + (lane & 3) * 2;
                    float v0 = w * (acc[mt][nidx][half * 2 + 0] + sbias[wn * 32 + cb]);
                    float v1 = w * (acc[mt][nidx][half * 2 + 1] + sbias[wn * 32 + cb + 1]);
                    *(float2*)(dst + cb) = make_float2(v0, v1);
                }
            }
        }
    }
}

// out = part0 + part1
__global__ __launch_bounds__(256) void combine_kernel(float* __restrict__ out) {
    size_t i = ((size_t)blockIdx.x * 256 + threadIdx.x) * 4;
    const float4 a = *(const float4*)(g_part + i);
    const float4 b = *(const float4*)(g_part + (size_t)NTOK * DIM + i);
    *(float4*)(out + i) = make_float4(a.x + b.x, a.y + b.y, a.z + b.z, a.w + b.w);
}

// ================= host =================
extern "C" void kernel_launch(void* const* d_in, const int* in_sizes, int n_in,
                              void* d_out, int out_size)
{
    const float* x  = (const float*)d_in[0];   // [4,2048,1024]
    const float* gW = (const float*)d_in[1];   // [1024,8]
    const float* gb = (const float*)d_in[2];   // [8]
    const float* eW = (const float*)d_in[3];   // [8,1024,1024]
    const float* eb = (const float*)d_in[4];   // [8,1024]
    float* out = (float*)d_out;
    (void)in_sizes; (void)n_in; (void)out_size;

    init_counts_kernel<<<1, 32>>>();
    gating_kernel<<<NTOK / 8, 256>>>(x, gW, gb);
    wcvt_kernel<<<(NE * DIM * DIM / 4) / 256, 256>>>(eW);

    cudaFuncSetAttribute(moe_gemm_kernel,
                         cudaFuncAttributeMaxDynamicSharedMemorySize, SM_TOTAL);
    dim3 grid(DIM / BN, NTOK / BM, NE);   // (8, 64, 8); inactive tiles exit early
    moe_gemm_kernel<<<grid, 256, SM_TOTAL>>>(eb);

    combine_kernel<<<(NTOK * DIM / 4) / 256, 256>>>(out);
}

// round 13
// speedup vs baseline: 2.1168x; 1.1952x over previous
#include <cuda_runtime.h>
#include <cuda_fp16.h>
#include <cstdint>
#include <math.h>

// Problem constants
#define NTOK 8192      // B*S
#define DIM  1024
#define NE   8
#define EPSV 1e-4f
#define WTHR 0.1f

// GEMM tile (R7-proven config)
#define BM 128
#define BN 128
#define BK 64
#define NKCH (DIM / BK)   // 16

// smem (dynamic, bytes)
#define ASTRIDE 144                   // 64 fp16 (128B) + 16B pad
#define BSTRIDE 272                   // 128 fp16 (256B) + 16B pad
#define ABUF    (128 * ASTRIDE)       // 18432
#define BBUF    (64 * BSTRIDE)        // 17408
#define OFF_A   0
#define OFF_B   ABUF
#define STAGE_SZ (ABUF + BBUF)        // 35840
#define SM_TOK   0
#define SM_WT    512
#define SM_BIAS  1024
#define SM_TILES 1536
#define SM_TOTAL (SM_TILES + 2 * STAGE_SZ)   // 73216

// -------- device scratch --------
__device__ int   g_cnt[NE];
__device__ int   g_tok[NE][NTOK];     // (token<<1) | slot
__device__ float g_wt [NE][NTOK];
__device__ __half g_xh[(size_t)NTOK * DIM];
__device__ __half g_wh[(size_t)NE * DIM * DIM];   // natural [e][d][f]
__device__ float g_part[2ull * NTOK * DIM];

// -------- helpers --------
__device__ __forceinline__ uint32_t smem_u32(const void* p) {
    uint32_t a;
    asm("{ .reg .u64 t; cvta.to.shared.u64 t, %1; cvt.u32.u64 %0, t; }" : "=r"(a) : "l"(p));
    return a;
}
__device__ __forceinline__ void ldsm_x4(uint32_t* r, uint32_t addr) {
    asm volatile("ldmatrix.sync.aligned.m8n8.x4.shared.b16 {%0,%1,%2,%3}, [%4];"
                 : "=r"(r[0]), "=r"(r[1]), "=r"(r[2]), "=r"(r[3]) : "r"(addr));
}
__device__ __forceinline__ void ldsm_x4_t(uint32_t* r, uint32_t addr) {
    asm volatile("ldmatrix.sync.aligned.m8n8.x4.trans.shared.b16 {%0,%1,%2,%3}, [%4];"
                 : "=r"(r[0]), "=r"(r[1]), "=r"(r[2]), "=r"(r[3]) : "r"(addr));
}
__device__ __forceinline__ void mma_f16(float* d, const uint32_t* a, uint32_t b0, uint32_t b1) {
    asm volatile(
        "mma.sync.aligned.m16n8k16.row.col.f32.f16.f16.f32 "
        "{%0,%1,%2,%3}, {%4,%5,%6,%7}, {%8,%9}, {%0,%1,%2,%3};"
        : "+f"(d[0]), "+f"(d[1]), "+f"(d[2]), "+f"(d[3])
        : "r"(a[0]), "r"(a[1]), "r"(a[2]), "r"(a[3]), "r"(b0), "r"(b1));
}
#define CPA16(dst, src) \
    asm volatile("cp.async.cg.shared.global [%0], [%1], 16;" :: "r"(dst), "l"(src) : "memory")
#define CPA_COMMIT() asm volatile("cp.async.commit_group;" ::: "memory")
#define CPA_WAIT0()  asm volatile("cp.async.wait_group 0;" ::: "memory")

// ================= kernels =================

__global__ void init_counts_kernel() {
    if (threadIdx.x < NE) g_cnt[threadIdx.x] = 0;
}

// gating: one warp per token, strided loads (R7-exact; NOT fused with conversion)
__global__ __launch_bounds__(256) void gating_kernel(
    const float* __restrict__ x, const float* __restrict__ gW, const float* __restrict__ gb)
{
    const int warp = threadIdx.x >> 5;
    const int lane = threadIdx.x & 31;
    const int t = blockIdx.x * 8 + warp;
    if (t >= NTOK) return;
    const float* xr = x + (size_t)t * DIM;

    float s[NE];
#pragma unroll
    for (int e = 0; e < NE; e++) s[e] = 0.0f;
    for (int d = lane; d < DIM; d += 32) {
        float xv = xr[d];
        const float* gr = gW + d * NE;
#pragma unroll
        for (int e = 0; e < NE; e++) s[e] = fmaf(xv, gr[e], s[e]);
    }
#pragma unroll
    for (int e = 0; e < NE; e++) {
#pragma unroll
        for (int off = 16; off > 0; off >>= 1)
            s[e] += __shfl_xor_sync(0xffffffffu, s[e], off);
    }
    if (lane == 0) {
        float p[NE];
        float m = -1e30f;
#pragma unroll
        for (int e = 0; e < NE; e++) {
            float sc = fmaxf(s[e] + gb[e], EPSV);
            p[e] = sc; m = fmaxf(m, sc);
        }
        float sum = 0.0f;
#pragma unroll
        for (int e = 0; e < NE; e++) { p[e] = expf(p[e] - m); sum += p[e]; }
        float inv = 1.0f / sum;
#pragma unroll
        for (int e = 0; e < NE; e++) p[e] *= inv;

        int i0 = 0; float b0 = p[0];
#pragma unroll
        for (int e = 1; e < NE; e++) if (p[e] > b0) { b0 = p[e]; i0 = e; }
        int i1 = (i0 == 0) ? 1 : 0; float b1 = -1.0f;
#pragma unroll
        for (int e = 0; e < NE; e++) if (e != i0 && p[e] > b1) { b1 = p[e]; i1 = e; }

        float w0 = fmaxf(b0, WTHR);
        float w1 = fmaxf(b1, WTHR);
        float invtot = 1.0f / (w0 + w1);
        float c0 = w0 * invtot * 0.5f;    // fold /K
        float c1 = w1 * invtot * 0.5f;

        int p0 = atomicAdd(&g_cnt[i0], 1);
        g_tok[i0][p0] = (t << 1) | 0; g_wt[i0][p0] = c0;
        int p1 = atomicAdd(&g_cnt[i1], 1);
        g_tok[i1][p1] = (t << 1) | 1; g_wt[i1][p1] = c1;
    }
}

// fp32 -> fp16 conversion for BOTH x and W (single kernel, block-uniform branch)
// blocks [0, NXB): x -> g_xh ; blocks [NXB, NXB+NWB): eW -> g_wh
#define NXB ((NTOK * DIM / 4) / 256)          // 8192
#define NWB ((NE * DIM * DIM / 4) / 256)      // 8192
__global__ __launch_bounds__(256) void cvt_kernel(
    const float* __restrict__ x, const float* __restrict__ W)
{
    if (blockIdx.x < NXB) {
        size_t i = ((size_t)blockIdx.x * 256 + threadIdx.x) * 4;
        float4 v = *(const float4*)(x + i);
        __half2 h0 = __float22half2_rn(make_float2(v.x, v.y));
        __half2 h1 = __float22half2_rn(make_float2(v.z, v.w));
        *(uint2*)(g_xh + i) = make_uint2(*(uint32_t*)&h0, *(uint32_t*)&h1);
    } else {
        size_t i = ((size_t)(blockIdx.x - NXB) * 256 + threadIdx.x) * 4;
        float4 v = *(const float4*)(W + i);
        __half2 h0 = __float22half2_rn(make_float2(v.x, v.y));
        __half2 h1 = __float22half2_rn(make_float2(v.z, v.w));
        *(uint2*)(g_wh + i) = make_uint2(*(uint32_t*)&h0, *(uint32_t*)&h1);
    }
}

// -------- fp16 expert GEMM, BM=128 x BN=128, full-K, 2-stage cp.async (R7-exact) --------
__global__ __launch_bounds__(256) void moe_gemm_kernel(const float* __restrict__ eb)
{
    extern __shared__ char smem[];
    const int e   = blockIdx.z;
    const int cnt = g_cnt[e];
    const int m0  = blockIdx.y * BM;
    if (m0 >= cnt) return;
    const int f0  = blockIdx.x * BN;

    const uint32_t sb = smem_u32(smem);
    const int tid  = threadIdx.x;
    const int lane = tid & 31;
    const int wid  = tid >> 5;
    const int wm   = wid & 1;     // 2 warp rows (64 m)
    const int wn   = wid >> 1;    // 4 warp cols (32 n)

    int*   stok  = (int*)(smem + SM_TOK);
    float* swt   = (float*)(smem + SM_WT);
    float* sbias = (float*)(smem + SM_BIAS);
    if (tid < BM) {
        int idx = m0 + tid;
        stok[tid] = (idx < cnt) ? g_tok[e][idx] : 0;
        swt[tid]  = (idx < cnt) ? g_wt[e][idx]  : 0.0f;
        sbias[tid] = eb[(size_t)e * DIM + f0 + tid];
    }
    __syncthreads();

    // copy mappings
    int      atokr[4];
    uint32_t adst[4];
    const int acol = tid & 7;
#pragma unroll
    for (int j = 0; j < 4; j++) {
        int idx = tid + j * 256;
        int row = idx >> 3;
        atokr[j] = stok[row] >> 1;
        adst[j]  = (uint32_t)(row * ASTRIDE + acol * 16);
    }
    const int bcol = tid & 15;
    int      brow[4];
    uint32_t bdst[4];
#pragma unroll
    for (int j = 0; j < 4; j++) {
        int idx = tid + j * 256;
        brow[j] = idx >> 4;
        bdst[j] = (uint32_t)(brow[j] * BSTRIDE + bcol * 16);
    }
    const __half* Wh = g_wh + (size_t)e * DIM * DIM + f0 + bcol * 8;

    // prologue: chunk 0 -> stage 0
    {
        const uint32_t s0 = sb + SM_TILES;
#pragma unroll
        for (int j = 0; j < 4; j++)
            CPA16(s0 + OFF_A + adst[j], g_xh + (size_t)atokr[j] * DIM + acol * 8);
#pragma unroll
        for (int j = 0; j < 4; j++)
            CPA16(s0 + OFF_B + bdst[j], Wh + (size_t)brow[j] * DIM);
        CPA_COMMIT();
    }

    float acc[4][4][4];
#pragma unroll
    for (int i = 0; i < 4; i++)
#pragma unroll
        for (int jj = 0; jj < 4; jj++)
#pragma unroll
            for (int r = 0; r < 4; r++) acc[i][jj][r] = 0.0f;

    const uint32_t a_off = (uint32_t)((wm * 64 + (lane & 15)) * ASTRIDE + ((lane >> 4) & 1) * 16);
    const uint32_t b_off = (uint32_t)((lane & 15) * BSTRIDE + wn * 64 + ((lane >> 4) & 1) * 16);

    for (int c = 0; c < NKCH; c++) {
        CPA_WAIT0();
        __syncthreads();

        if (c + 1 < NKCH) {
            const uint32_t sn = sb + SM_TILES + ((c + 1) & 1) * STAGE_SZ;
            const int k0 = (c + 1) * BK;
#pragma unroll
            for (int j = 0; j < 4; j++)
                CPA16(sn + OFF_A + adst[j], g_xh + (size_t)atokr[j] * DIM + k0 + acol * 8);
#pragma unroll
            for (int j = 0; j < 4; j++)
                CPA16(sn + OFF_B + bdst[j], Wh + (size_t)(k0 + brow[j]) * DIM);
            CPA_COMMIT();
        }

        const uint32_t sc = sb + SM_TILES + (c & 1) * STAGE_SZ;
#pragma unroll
        for (int ks = 0; ks < 4; ks++) {
            uint32_t ah[4][4];
#pragma unroll
            for (int mt = 0; mt < 4; mt++) {
                uint32_t ad = sc + OFF_A + a_off + (uint32_t)(mt * 16 * ASTRIDE + ks * 32);
                ldsm_x4(ah[mt], ad);
            }
#pragma unroll
            for (int nb2 = 0; nb2 < 2; nb2++) {
                uint32_t bh[4];
                uint32_t bd = sc + OFF_B + b_off + (uint32_t)(ks * 16 * BSTRIDE + nb2 * 32);
                ldsm_x4_t(bh, bd);
#pragma unroll
                for (int mt = 0; mt < 4; mt++) {
                    mma_f16(acc[mt][nb2 * 2 + 0], ah[mt], bh[0], bh[1]);
                    mma_f16(acc[mt][nb2 * 2 + 1], ah[mt], bh[2], bh[3]);
                }
            }
        }
        __syncthreads();
    }

    // ---- epilogue: write-once into g_part[slot][tok][f] ----
#pragma unroll
    for (int mt = 0; mt < 4; mt++) {
#pragma unroll
        for (int half = 0; half < 2; half++) {
            int m = wm * 64 + mt * 16 + (lane >> 2) + half * 8;
            if (m0 + m < cnt) {
                int te = stok[m];
                float w = swt[m];
                float* dst = g_part + ((size_t)(te & 1) * NTOK + (size_t)(te >> 1)) * DIM
                           + f0 + wn * 32;
#pragma unroll
                for (int nidx = 0; nidx < 4; nidx++) {
                    int cb = nidx * 8 + (lane & 3) * 2;
                    float v0 = w * (acc[mt][nidx][half * 2 + 0] + sbias[wn * 32 + cb]);
                    float v1 = w * (acc[mt][nidx][half * 2 + 1] + sbias[wn * 32 + cb + 1]);
                    *(float2*)(dst + cb) = make_float2(v0, v1);
                }
            }
        }
    }
}

// out = part0 + part1
__global__ __launch_bounds__(256) void combine_kernel(float* __restrict__ out) {
    size_t i = ((size_t)blockIdx.x * 256 + threadIdx.x) * 4;
    const float4 a = *(const float4*)(g_part + i);
    const float4 b = *(const float4*)(g_part + (size_t)NTOK * DIM + i);
    *(float4*)(out + i) = make_float4(a.x + b.x, a.y + b.y, a.z + b.z, a.w + b.w);
}

// ================= host =================
extern "C" void kernel_launch(void* const* d_in, const int* in_sizes, int n_in,
                              void* d_out, int out_size)
{
    const float* x  = (const float*)d_in[0];   // [4,2048,1024]
    const float* gW = (const float*)d_in[1];   // [1024,8]
    const float* gb = (const float*)d_in[2];   // [8]
    const float* eW = (const float*)d_in[3];   // [8,1024,1024]
    const float* eb = (const float*)d_in[4];   // [8,1024]
    float* out = (float*)d_out;
    (void)in_sizes; (void)n_in; (void)out_size;

    init_counts_kernel<<<1, 32>>>();
    gating_kernel<<<NTOK / 8, 256>>>(x, gW, gb);
    cvt_kernel<<<NXB + NWB, 256>>>(x, eW);

    cudaFuncSetAttribute(moe_gemm_kernel,
                         cudaFuncAttributeMaxDynamicSharedMemorySize, SM_TOTAL);
    dim3 grid(DIM / BN, NTOK / BM, NE);   // (8, 64, 8); inactive tiles exit early
    moe_gemm_kernel<<<grid, 256, SM_TOTAL>>>(eb);

    combine_kernel<<<(NTOK * DIM / 4) / 256, 256>>>(out);
}

// round 14
// speedup vs baseline: 3.1591x; 1.4923x over previous
#include <cuda_runtime.h>
#include <cuda_fp16.h>
#include <cstdint>
#include <math.h>

// Problem constants
#define NTOK 8192      // B*S
#define DIM  1024
#define NE   8
#define EPSV 1e-4f
#define WTHR 0.1f

// GEMM tile (R7-proven config)
#define BM 128
#define BN 128
#define BK 64
#define NKCH (DIM / BK)   // 16

// smem (dynamic, bytes)
#define ASTRIDE 144                   // 64 fp16 (128B) + 16B pad
#define BSTRIDE 272                   // 128 fp16 (256B) + 16B pad
#define ABUF    (128 * ASTRIDE)       // 18432
#define BBUF    (64 * BSTRIDE)        // 17408
#define OFF_A   0
#define OFF_B   ABUF
#define STAGE_SZ (ABUF + BBUF)        // 35840
#define SM_TOK   0
#define SM_WT    512
#define SM_BIAS  1024
#define SM_TILES 1536
#define SM_TOTAL (SM_TILES + 2 * STAGE_SZ)   // 73216

// -------- device scratch --------
__device__ int   g_cnt[NE];
__device__ int   g_tok[NE][NTOK];     // (token<<1) | slot
__device__ float g_wt [NE][NTOK];
__device__ __half g_xh[(size_t)NTOK * DIM];
__device__ __half g_wh[(size_t)NE * DIM * DIM];   // natural [e][d][f]
__device__ float g_part[2ull * NTOK * DIM];

// -------- helpers --------
__device__ __forceinline__ uint32_t smem_u32(const void* p) {
    uint32_t a;
    asm("{ .reg .u64 t; cvta.to.shared.u64 t, %1; cvt.u32.u64 %0, t; }" : "=r"(a) : "l"(p));
    return a;
}
__device__ __forceinline__ void ldsm_x4(uint32_t* r, uint32_t addr) {
    asm volatile("ldmatrix.sync.aligned.m8n8.x4.shared.b16 {%0,%1,%2,%3}, [%4];"
                 : "=r"(r[0]), "=r"(r[1]), "=r"(r[2]), "=r"(r[3]) : "r"(addr));
}
__device__ __forceinline__ void ldsm_x4_t(uint32_t* r, uint32_t addr) {
    asm volatile("ldmatrix.sync.aligned.m8n8.x4.trans.shared.b16 {%0,%1,%2,%3}, [%4];"
                 : "=r"(r[0]), "=r"(r[1]), "=r"(r[2]), "=r"(r[3]) : "r"(addr));
}
__device__ __forceinline__ void mma_f16(float* d, const uint32_t* a, uint32_t b0, uint32_t b1) {
    asm volatile(
        "mma.sync.aligned.m16n8k16.row.col.f32.f16.f16.f32 "
        "{%0,%1,%2,%3}, {%4,%5,%6,%7}, {%8,%9}, {%0,%1,%2,%3};"
        : "+f"(d[0]), "+f"(d[1]), "+f"(d[2]), "+f"(d[3])
        : "r"(a[0]), "r"(a[1]), "r"(a[2]), "r"(a[3]), "r"(b0), "r"(b1));
}
#define CPA16(dst, src) \
    asm volatile("cp.async.cg.shared.global [%0], [%1], 16;" :: "r"(dst), "l"(src) : "memory")
#define CPA_COMMIT() asm volatile("cp.async.commit_group;" ::: "memory")
#define CPA_WAIT0()  asm volatile("cp.async.wait_group 0;" ::: "memory")

// ================= kernels =================

__global__ void init_counts_kernel() {
    if (threadIdx.x < NE) g_cnt[threadIdx.x] = 0;
}

// gating: one warp per token, strided loads (R7-exact)
__global__ __launch_bounds__(256) void gating_kernel(
    const float* __restrict__ x, const float* __restrict__ gW, const float* __restrict__ gb)
{
    const int warp = threadIdx.x >> 5;
    const int lane = threadIdx.x & 31;
    const int t = blockIdx.x * 8 + warp;
    if (t >= NTOK) return;
    const float* xr = x + (size_t)t * DIM;

    float s[NE];
#pragma unroll
    for (int e = 0; e < NE; e++) s[e] = 0.0f;
    for (int d = lane; d < DIM; d += 32) {
        float xv = xr[d];
        const float* gr = gW + d * NE;
#pragma unroll
        for (int e = 0; e < NE; e++) s[e] = fmaf(xv, gr[e], s[e]);
    }
#pragma unroll
    for (int e = 0; e < NE; e++) {
#pragma unroll
        for (int off = 16; off > 0; off >>= 1)
            s[e] += __shfl_xor_sync(0xffffffffu, s[e], off);
    }
    if (lane == 0) {
        float p[NE];
        float m = -1e30f;
#pragma unroll
        for (int e = 0; e < NE; e++) {
            float sc = fmaxf(s[e] + gb[e], EPSV);
            p[e] = sc; m = fmaxf(m, sc);
        }
        float sum = 0.0f;
#pragma unroll
        for (int e = 0; e < NE; e++) { p[e] = expf(p[e] - m); sum += p[e]; }
        float inv = 1.0f / sum;
#pragma unroll
        for (int e = 0; e < NE; e++) p[e] *= inv;

        int i0 = 0; float b0 = p[0];
#pragma unroll
        for (int e = 1; e < NE; e++) if (p[e] > b0) { b0 = p[e]; i0 = e; }
        int i1 = (i0 == 0) ? 1 : 0; float b1 = -1.0f;
#pragma unroll
        for (int e = 0; e < NE; e++) if (e != i0 && p[e] > b1) { b1 = p[e]; i1 = e; }

        float w0 = fmaxf(b0, WTHR);
        float w1 = fmaxf(b1, WTHR);
        float invtot = 1.0f / (w0 + w1);
        float c0 = w0 * invtot * 0.5f;    // fold /K
        float c1 = w1 * invtot * 0.5f;

        int p0 = atomicAdd(&g_cnt[i0], 1);
        g_tok[i0][p0] = (t << 1) | 0; g_wt[i0][p0] = c0;
        int p1 = atomicAdd(&g_cnt[i1], 1);
        g_tok[i1][p1] = (t << 1) | 1; g_wt[i1][p1] = c1;
    }
}

// fp32 -> fp16 converters (R7-exact: two separate streaming kernels)
__global__ __launch_bounds__(256) void xcvt_kernel(const float* __restrict__ x) {
    size_t i = ((size_t)blockIdx.x * 256 + threadIdx.x) * 4;
    float4 v = *(const float4*)(x + i);
    __half2 h0 = __float22half2_rn(make_float2(v.x, v.y));
    __half2 h1 = __float22half2_rn(make_float2(v.z, v.w));
    *(uint2*)(g_xh + i) = make_uint2(*(uint32_t*)&h0, *(uint32_t*)&h1);
}
__global__ __launch_bounds__(256) void wcvt_kernel(const float* __restrict__ W) {
    size_t i = ((size_t)blockIdx.x * 256 + threadIdx.x) * 4;
    float4 v = *(const float4*)(W + i);
    __half2 h0 = __float22half2_rn(make_float2(v.x, v.y));
    __half2 h1 = __float22half2_rn(make_float2(v.z, v.w));
    *(uint2*)(g_wh + i) = make_uint2(*(uint32_t*)&h0, *(uint32_t*)&h1);
}

// -------- fp16 expert GEMM, BM=128 x BN=128, full-K, 2-stage cp.async --------
// R7-exact except: redundant bottom __syncthreads removed (top WAIT0+sync of
// iter c+1 already orders all compute of iter c before stage reuse).
__global__ __launch_bounds__(256) void moe_gemm_kernel(const float* __restrict__ eb)
{
    extern __shared__ char smem[];
    const int e   = blockIdx.z;
    const int cnt = g_cnt[e];
    const int m0  = blockIdx.y * BM;
    if (m0 >= cnt) return;
    const int f0  = blockIdx.x * BN;

    const uint32_t sb = smem_u32(smem);
    const int tid  = threadIdx.x;
    const int lane = tid & 31;
    const int wid  = tid >> 5;
    const int wm   = wid & 1;     // 2 warp rows (64 m)
    const int wn   = wid >> 1;    // 4 warp cols (32 n)

    int*   stok  = (int*)(smem + SM_TOK);
    float* swt   = (float*)(smem + SM_WT);
    float* sbias = (float*)(smem + SM_BIAS);
    if (tid < BM) {
        int idx = m0 + tid;
        stok[tid] = (idx < cnt) ? g_tok[e][idx] : 0;
        swt[tid]  = (idx < cnt) ? g_wt[e][idx]  : 0.0f;
        sbias[tid] = eb[(size_t)e * DIM + f0 + tid];
    }
    __syncthreads();

    // copy mappings
    int      atokr[4];
    uint32_t adst[4];
    const int acol = tid & 7;
#pragma unroll
    for (int j = 0; j < 4; j++) {
        int idx = tid + j * 256;
        int row = idx >> 3;
        atokr[j] = stok[row] >> 1;
        adst[j]  = (uint32_t)(row * ASTRIDE + acol * 16);
    }
    const int bcol = tid & 15;
    int      brow[4];
    uint32_t bdst[4];
#pragma unroll
    for (int j = 0; j < 4; j++) {
        int idx = tid + j * 256;
        brow[j] = idx >> 4;
        bdst[j] = (uint32_t)(brow[j] * BSTRIDE + bcol * 16);
    }
    const __half* Wh = g_wh + (size_t)e * DIM * DIM + f0 + bcol * 8;

    // prologue: chunk 0 -> stage 0
    {
        const uint32_t s0 = sb + SM_TILES;
#pragma unroll
        for (int j = 0; j < 4; j++)
            CPA16(s0 + OFF_A + adst[j], g_xh + (size_t)atokr[j] * DIM + acol * 8);
#pragma unroll
        for (int j = 0; j < 4; j++)
            CPA16(s0 + OFF_B + bdst[j], Wh + (size_t)brow[j] * DIM);
        CPA_COMMIT();
    }

    float acc[4][4][4];
#pragma unroll
    for (int i = 0; i < 4; i++)
#pragma unroll
        for (int jj = 0; jj < 4; jj++)
#pragma unroll
            for (int r = 0; r < 4; r++) acc[i][jj][r] = 0.0f;

    const uint32_t a_off = (uint32_t)((wm * 64 + (lane & 15)) * ASTRIDE + ((lane >> 4) & 1) * 16);
    const uint32_t b_off = (uint32_t)((lane & 15) * BSTRIDE + wn * 64 + ((lane >> 4) & 1) * 16);

    for (int c = 0; c < NKCH; c++) {
        CPA_WAIT0();
        __syncthreads();   // chunk c resident; all warps past compute of chunk c-1

        if (c + 1 < NKCH) {
            const uint32_t sn = sb + SM_TILES + ((c + 1) & 1) * STAGE_SZ;
            const int k0 = (c + 1) * BK;
#pragma unroll
            for (int j = 0; j < 4; j++)
                CPA16(sn + OFF_A + adst[j], g_xh + (size_t)atokr[j] * DIM + k0 + acol * 8);
#pragma unroll
            for (int j = 0; j < 4; j++)
                CPA16(sn + OFF_B + bdst[j], Wh + (size_t)(k0 + brow[j]) * DIM);
            CPA_COMMIT();
        }

        const uint32_t sc = sb + SM_TILES + (c & 1) * STAGE_SZ;
#pragma unroll
        for (int ks = 0; ks < 4; ks++) {
            uint32_t ah[4][4];
#pragma unroll
            for (int mt = 0; mt < 4; mt++) {
                uint32_t ad = sc + OFF_A + a_off + (uint32_t)(mt * 16 * ASTRIDE + ks * 32);
                ldsm_x4(ah[mt], ad);
            }
#pragma unroll
            for (int nb2 = 0; nb2 < 2; nb2++) {
                uint32_t bh[4];
                uint32_t bd = sc + OFF_B + b_off + (uint32_t)(ks * 16 * BSTRIDE + nb2 * 32);
                ldsm_x4_t(bh, bd);
#pragma unroll
                for (int mt = 0; mt < 4; mt++) {
                    mma_f16(acc[mt][nb2 * 2 + 0], ah[mt], bh[0], bh[1]);
                    mma_f16(acc[mt][nb2 * 2 + 1], ah[mt], bh[2], bh[3]);
                }
            }
        }
        // (bottom __syncthreads removed: next iteration's top barrier provides
        //  the ordering before stage (c&1) is overwritten at iteration c+2)
    }

    // ---- epilogue: write-once into g_part[slot][tok][f] ----
#pragma unroll
    for (int mt = 0; mt < 4; mt++) {
#pragma unroll
        for (int half = 0; half < 2; half++) {
            int m = wm * 64 + mt * 16 + (lane >> 2) + half * 8;
            if (m0 + m < cnt) {
                int te = stok[m];
                float w = swt[m];
                float* dst = g_part + ((size_t)(te & 1) * NTOK + (size_t)(te >> 1)) * DIM
                           + f0 + wn * 32;
#pragma unroll
                for (int nidx = 0; nidx < 4; nidx++) {
                    int cb = nidx * 8 + (lane & 3) * 2;
                    float v0 = w * (acc[mt][nidx][half * 2 + 0] + sbias[wn * 32 + cb]);
                    float v1 = w * (acc[mt][nidx][half * 2 + 1] + sbias[wn * 32 + cb + 1]);
                    *(float2*)(dst + cb) = make_float2(v0, v1);
                }
            }
        }
    }
}

// out = part0 + part1
__global__ __launch_bounds__(256) void combine_kernel(float* __restrict__ out) {
    size_t i = ((size_t)blockIdx.x * 256 + threadIdx.x) * 4;
    const float4 a = *(const float4*)(g_part + i);
    const float4 b = *(const float4*)(g_part + (size_t)NTOK * DIM + i);
    *(float4*)(out + i) = make_float4(a.x + b.x, a.y + b.y, a.z + b.z, a.w + b.w);
}

// ================= host =================
extern "C" void kernel_launch(void* const* d_in, const int* in_sizes, int n_in,
                              void* d_out, int out_size)
{
    const float* x  = (const float*)d_in[0];   // [4,2048,1024]
    const float* gW = (const float*)d_in[1];   // [1024,8]
    const float* gb = (const float*)d_in[2];   // [8]
    const float* eW = (const float*)d_in[3];   // [8,1024,1024]
    const float* eb = (const float*)d_in[4];   // [8,1024]
    float* out = (float*)d_out;
    (void)in_sizes; (void)n_in; (void)out_size;

    init_counts_kernel<<<1, 32>>>();
    gating_kernel<<<NTOK / 8, 256>>>(x, gW, gb);
    xcvt_kernel<<<(NTOK * DIM / 4) / 256, 256>>>(x);
    wcvt_kernel<<<(NE * DIM * DIM / 4) / 256, 256>>>(eW);

    cudaFuncSetAttribute(moe_gemm_kernel,
                         cudaFuncAttributeMaxDynamicSharedMemorySize, SM_TOTAL);
    dim3 grid(DIM / BN, NTOK / BM, NE);   // (8, 64, 8); inactive tiles exit early
    moe_gemm_kernel<<<grid, 256, SM_TOTAL>>>(eb);

    combine_kernel<<<(NTOK * DIM / 4) / 256, 256>>>(out);
}